// round 13
// baseline (speedup 1.0000x reference)
#include <cuda_runtime.h>
#include <cuda_fp16.h>
#include <cstdint>

// Problem constants (match reference_code)
#define NROWS 100001
#define DIM   64
#define NNZ_E 3200000
#define ND    (NROWS * DIM)          // floats per segment
#define ND4   (ND / 4)               // float4 / uint2 granules per segment
#define SCAN_B 1024
#define NBLK  ((NROWS + SCAN_B - 1) / SCAN_B)   // 98

// ---------------------------------------------------------------------------
// Static device scratch. Referenced ONLY inside device code (R6 lesson).
// ---------------------------------------------------------------------------
__device__ int   g_counts[NROWS];       // histogram, then scatter cursors
__device__ int   g_rowptr[NROWS + 1];   // CSR row pointers (exclusive scan)
__device__ int   g_partials[NBLK];      // scan block totals
__device__ int2  g_meta[NNZ_E];         // CSR-ordered (col, val-bits), 25.6MB
__device__ uint2 g_embh[ND4];           // emb in fp16 (4 halves/uint2), 12.8MB
__device__ uint2 g_e1h[ND4];            // e1  in fp16, 12.8MB

// ---------------------------------------------------------------------------
// Side stream + events (static init: no device memory, outside capture).
// ---------------------------------------------------------------------------
static cudaStream_t g_s2 = nullptr;
static cudaEvent_t  g_ev_fork = nullptr;
static cudaEvent_t  g_ev_join = nullptr;
namespace {
struct StreamInit {
    StreamInit() {
        cudaStreamCreateWithFlags(&g_s2, cudaStreamNonBlocking);
        cudaEventCreateWithFlags(&g_ev_fork, cudaEventDisableTiming);
        cudaEventCreateWithFlags(&g_ev_join, cudaEventDisableTiming);
    }
};
StreamInit g_stream_init;
}

// ---------------------------------------------------------------------------
// K0: zero histogram (must complete before conv_hist increments).
// ---------------------------------------------------------------------------
__global__ void zero_kernel()
{
    int i = blockIdx.x * blockDim.x + threadIdx.x;
    if (i < NROWS) g_counts[i] = 0;
    if (i == 0) g_rowptr[NROWS] = NNZ_E;
}

// ---------------------------------------------------------------------------
// K1: fused fp16-convert + hist (e0 copy moved to async D2D memcpy).
//   i < ND4:     embh = fp16(emb)
//   i < NNZ/4:   histogram 4 edges (ND4 = 1.6M >= NNZ/4 = 800K)
// ---------------------------------------------------------------------------
__global__ void conv_hist_kernel(const float4* __restrict__ emb,
                                 const int4* __restrict__ row4)
{
    int i = blockIdx.x * blockDim.x + threadIdx.x;
    if (i < ND4) {
        float4 v = __ldg(emb + i);
        __half2 h0 = __floats2half2_rn(v.x, v.y);
        __half2 h1 = __floats2half2_rn(v.z, v.w);
        uint2 u;
        u.x = *reinterpret_cast<unsigned*>(&h0);
        u.y = *reinterpret_cast<unsigned*>(&h1);
        g_embh[i] = u;
    }
    if (i < NNZ_E / 4) {
        int4 r = __ldg(row4 + i);
        atomicAdd(&g_counts[r.x], 1);
        atomicAdd(&g_counts[r.y], 1);
        atomicAdd(&g_counts[r.z], 1);
        atomicAdd(&g_counts[r.w], 1);
    }
}

// ---------------------------------------------------------------------------
// K2: per-block exclusive scan of counts; block totals to g_partials.
// ---------------------------------------------------------------------------
__global__ void scan1_kernel()
{
    __shared__ int s[SCAN_B];
    int gid = blockIdx.x * SCAN_B + threadIdx.x;
    int v = (gid < NROWS) ? g_counts[gid] : 0;
    s[threadIdx.x] = v;
    __syncthreads();
    #pragma unroll
    for (int off = 1; off < SCAN_B; off <<= 1) {
        int t = (threadIdx.x >= off) ? s[threadIdx.x - off] : 0;
        __syncthreads();
        s[threadIdx.x] += t;
        __syncthreads();
    }
    if (gid < NROWS) g_rowptr[gid] = s[threadIdx.x] - v;   // exclusive, block-local
    if (threadIdx.x == SCAN_B - 1) g_partials[blockIdx.x] = s[threadIdx.x];
}

// ---------------------------------------------------------------------------
// K3: each block reduces totals of preceding blocks (98 ints), adds base.
// ---------------------------------------------------------------------------
__global__ void scan3_kernel()
{
    __shared__ int s[128];
    int t = threadIdx.x;
    if (t < 128) s[t] = (t < blockIdx.x && t < NBLK) ? g_partials[t] : 0;
    __syncthreads();
    #pragma unroll
    for (int off = 64; off > 0; off >>= 1) {
        if (t < off) s[t] += s[t + off];
        __syncthreads();
    }
    int base = s[0];

    int gid = blockIdx.x * SCAN_B + t;
    if (gid < NROWS) {
        int p = g_rowptr[gid] + base;
        g_rowptr[gid] = p;
        g_counts[gid] = p;     // scatter cursor
    }
}

// ---------------------------------------------------------------------------
// K4: scatter edges into CSR order, 4 edges per thread (MLP=4 on atomics).
// ---------------------------------------------------------------------------
__global__ void scatter_kernel(const int4* __restrict__ row4,
                               const int4* __restrict__ col4,
                               const float4* __restrict__ vals4)
{
    int i = blockIdx.x * blockDim.x + threadIdx.x;
    if (i < NNZ_E / 4) {
        int4   r = __ldg(row4 + i);
        int4   c = __ldg(col4 + i);
        float4 v = __ldg(vals4 + i);
        int p0 = atomicAdd(&g_counts[r.x], 1);
        int p1 = atomicAdd(&g_counts[r.y], 1);
        int p2 = atomicAdd(&g_counts[r.z], 1);
        int p3 = atomicAdd(&g_counts[r.w], 1);
        g_meta[p0] = make_int2(c.x, __float_as_int(v.x));
        g_meta[p1] = make_int2(c.y, __float_as_int(v.y));
        g_meta[p2] = make_int2(c.z, __float_as_int(v.z));
        g_meta[p3] = make_int2(c.w, __float_as_int(v.w));
    }
}

// ---------------------------------------------------------------------------
// Helpers.
// ---------------------------------------------------------------------------
__device__ __forceinline__ void fma4(float4& acc, uint2 u, float v)
{
    float2 a = __half22float2(*reinterpret_cast<__half2*>(&u.x));
    float2 b = __half22float2(*reinterpret_cast<__half2*>(&u.y));
    acc.x = fmaf(v, a.x, acc.x); acc.y = fmaf(v, a.y, acc.y);
    acc.z = fmaf(v, b.x, acc.z); acc.w = fmaf(v, b.y, acc.w);
}

__device__ __forceinline__ float4 h4_to_f4(uint2 u)
{
    float2 a = __half22float2(*reinterpret_cast<__half2*>(&u.x));
    float2 b = __half22float2(*reinterpret_cast<__half2*>(&u.y));
    return make_float4(a.x, a.y, b.x, b.y);
}

// ---------------------------------------------------------------------------
// K5: CSR SpMM with FP16 GATHERS, fp32 accumulation — EXACT R9 inner loop
//     (3-deep pipeline; proven optimum across R8/R10/R11 — do not modify).
//   WRITE_H: also g_e1h[r,:] = fp16(y[r,:])   (layer 1 -> feeds layer 2)
//   FUSE:    also summed[r,:] = embh + e1h + y  (fp16 shadows; their
//            quantization is <3e-5 of |summed| since |e2| >> |e1| >> |e0|)
// ---------------------------------------------------------------------------
template <int SRC, bool WRITE_H, bool FUSE>
__global__ void spmm_csr_kernel(float4* __restrict__ y,
                                float4* __restrict__ summed)
{
    const uint2* __restrict__ xh = (SRC == 0) ? g_embh : g_e1h;

    int warp = (blockIdx.x * blockDim.x + threadIdx.x) >> 5;
    int lane = threadIdx.x & 31;
    int j    = lane & 15;        // uint2 slot within the 128B fp16 row
    int half = lane >> 4;        // 0 or 1: which edge of the pair
    if (warp >= NROWS) return;
    int r = warp;

    int beg = g_rowptr[r];
    int end = g_rowptr[r + 1];

    float4 acc = make_float4(0.f, 0.f, 0.f, 0.f);
    int e = beg + half;          // this thread's edge stream: e, e+2, e+4, ...

    // 3-deep: edges e, e+2, e+4 in flight -> 6 edges per warp concurrently
    for (; e + 4 < end; e += 6) {
        int2 m0 = __ldg(&g_meta[e]);
        int2 m1 = __ldg(&g_meta[e + 2]);
        int2 m2 = __ldg(&g_meta[e + 4]);
        uint2 u0 = __ldg(xh + (size_t)m0.x * 16 + j);
        uint2 u1 = __ldg(xh + (size_t)m1.x * 16 + j);
        uint2 u2 = __ldg(xh + (size_t)m2.x * 16 + j);
        fma4(acc, u0, __int_as_float(m0.y));
        fma4(acc, u1, __int_as_float(m1.y));
        fma4(acc, u2, __int_as_float(m2.y));
    }
    // 2-deep remainder
    if (e + 2 < end) {
        int2 m0 = __ldg(&g_meta[e]);
        int2 m1 = __ldg(&g_meta[e + 2]);
        uint2 u0 = __ldg(xh + (size_t)m0.x * 16 + j);
        uint2 u1 = __ldg(xh + (size_t)m1.x * 16 + j);
        fma4(acc, u0, __int_as_float(m0.y));
        fma4(acc, u1, __int_as_float(m1.y));
        e += 4;
    }
    if (e < end) {
        int2 m0 = __ldg(&g_meta[e]);
        uint2 u0 = __ldg(xh + (size_t)m0.x * 16 + j);
        fma4(acc, u0, __int_as_float(m0.y));
    }

    // combine the two half-warp partials
    acc.x += __shfl_xor_sync(0xffffffffu, acc.x, 16);
    acc.y += __shfl_xor_sync(0xffffffffu, acc.y, 16);
    acc.z += __shfl_xor_sync(0xffffffffu, acc.z, 16);
    acc.w += __shfl_xor_sync(0xffffffffu, acc.w, 16);

    if (half == 0) {
        size_t o = (size_t)r * 16 + j;
        y[o] = acc;
        if (WRITE_H) {
            __half2 h0 = __floats2half2_rn(acc.x, acc.y);
            __half2 h1 = __floats2half2_rn(acc.z, acc.w);
            uint2 u;
            u.x = *reinterpret_cast<unsigned*>(&h0);
            u.y = *reinterpret_cast<unsigned*>(&h1);
            g_e1h[o] = u;
        }
        if (FUSE) {
            float4 a = h4_to_f4(__ldg(&g_embh[o]));   // e0 (fp16 shadow)
            float4 b = h4_to_f4(__ldg(&g_e1h[o]));    // e1 (fp16 shadow)
            float4 s;
            s.x = a.x + b.x + acc.x;
            s.y = a.y + b.y + acc.y;
            s.z = a.z + b.z + acc.z;
            s.w = a.w + b.w + acc.w;
            summed[o] = s;
        }
    }
}

// ---------------------------------------------------------------------------
// Launch graph (no allocations; D2D async memcpy is allowed):
//   stream 2: e0 <- emb (copy, overlaps the atomic-bound hist chain)
//   stream 0: zero -> conv+hist -> scan1 -> scan3 -> scatter -> spmm1 -> spmm2
// ---------------------------------------------------------------------------
extern "C" void kernel_launch(void* const* d_in, const int* in_sizes, int n_in,
                              void* d_out, int out_size)
{
    const int*   row  = (const int*)d_in[0];
    const int*   col  = (const int*)d_in[1];
    const float* vals = (const float*)d_in[2];
    const float* emb  = (const float*)d_in[3];

    float* out = (float*)d_out;
    float4* summed = (float4*)out;
    float*  e0 = out + (size_t)ND;
    float4* e1 = (float4*)(out + (size_t)2 * ND);
    float4* e2 = (float4*)(out + (size_t)3 * ND);

    const int TPB = 256;

    // fork: side stream carries the e0 copy
    cudaEventRecord(g_ev_fork, 0);
    cudaStreamWaitEvent(g_s2, g_ev_fork, 0);
    cudaMemcpyAsync(e0, emb, (size_t)ND * sizeof(float),
                    cudaMemcpyDeviceToDevice, g_s2);
    cudaEventRecord(g_ev_join, g_s2);

    // main chain: CSR build + fp16 conversion
    zero_kernel<<<(NROWS + TPB - 1) / TPB, TPB>>>();
    conv_hist_kernel<<<(ND4 + TPB - 1) / TPB, TPB>>>(
        (const float4*)emb, (const int4*)row);
    scan1_kernel<<<NBLK, SCAN_B>>>();
    scan3_kernel<<<NBLK, SCAN_B>>>();
    scatter_kernel<<<(NNZ_E / 4 + TPB - 1) / TPB, TPB>>>(
        (const int4*)row, (const int4*)col, (const float4*)vals);

    const int WARPS_PER_BLOCK = TPB / 32;
    int spmm_blocks = (NROWS + WARPS_PER_BLOCK - 1) / WARPS_PER_BLOCK;

    // layer 1: e1 = A @ emb (gather g_embh), also g_e1h = fp16(e1)
    spmm_csr_kernel<0, true, false><<<spmm_blocks, TPB>>>(e1, nullptr);

    // join before spmm2 (free: copy finished long ago; keeps graph ordered)
    cudaStreamWaitEvent(0, g_ev_join, 0);

    // layer 2: e2 = A @ e1 (gather g_e1h), fused summed = e0 + e1 + e2
    spmm_csr_kernel<1, false, true><<<spmm_blocks, TPB>>>(e2, summed);
}

// round 14
// speedup vs baseline: 1.0881x; 1.0881x over previous
#include <cuda_runtime.h>
#include <cuda_fp16.h>
#include <cstdint>

// Problem constants (match reference_code)
#define NROWS 100001
#define DIM   64
#define NNZ_E 3200000
#define ND    (NROWS * DIM)          // floats per segment
#define ND4   (ND / 4)               // float4 / uint2 granules per segment
#define SCAN_B 1024
#define NBLK  ((NROWS + SCAN_B - 1) / SCAN_B)   // 98

// ---------------------------------------------------------------------------
// Static device scratch. Referenced ONLY inside device code (R6 lesson:
// passing a __device__ symbol as a host-side kernel arg gives garbage).
// ---------------------------------------------------------------------------
__device__ int   g_counts[NROWS];       // histogram, then scatter cursors
__device__ int   g_rowptr[NROWS + 1];   // CSR row pointers (exclusive scan)
__device__ int   g_partials[NBLK];      // scan block totals
__device__ int2  g_meta[NNZ_E];         // CSR-ordered (col, val-bits), 25.6MB
__device__ uint2 g_embh[ND4];           // emb in fp16 (4 halves/uint2), 12.8MB
__device__ uint2 g_e1h[ND4];            // e1  in fp16, 12.8MB

// ---------------------------------------------------------------------------
// K0: zero histogram (must complete before prep_hist increments).
// ---------------------------------------------------------------------------
__global__ void zero_kernel()
{
    int i = blockIdx.x * blockDim.x + threadIdx.x;
    if (i < NROWS) g_counts[i] = 0;
    if (i == 0) g_rowptr[NROWS] = NNZ_E;
}

// ---------------------------------------------------------------------------
// K1: fused prep + hist.
//   i < ND4:     e0 = emb (fp32 copy), embh = fp16(emb)
//   i < NNZ/4:   histogram 4 edges (ND4 = 1.6M >= NNZ/4 = 800K)
// ---------------------------------------------------------------------------
__global__ void prep_hist_kernel(const float4* __restrict__ emb,
                                 float4* __restrict__ e0,
                                 const int4* __restrict__ row4)
{
    int i = blockIdx.x * blockDim.x + threadIdx.x;
    if (i < ND4) {
        float4 v = __ldg(emb + i);
        e0[i] = v;
        __half2 h0 = __floats2half2_rn(v.x, v.y);
        __half2 h1 = __floats2half2_rn(v.z, v.w);
        uint2 u;
        u.x = *reinterpret_cast<unsigned*>(&h0);
        u.y = *reinterpret_cast<unsigned*>(&h1);
        g_embh[i] = u;
    }
    if (i < NNZ_E / 4) {
        int4 r = __ldg(row4 + i);
        atomicAdd(&g_counts[r.x], 1);
        atomicAdd(&g_counts[r.y], 1);
        atomicAdd(&g_counts[r.z], 1);
        atomicAdd(&g_counts[r.w], 1);
    }
}

// ---------------------------------------------------------------------------
// K2: per-block exclusive scan of counts; block totals to g_partials.
// ---------------------------------------------------------------------------
__global__ void scan1_kernel()
{
    __shared__ int s[SCAN_B];
    int gid = blockIdx.x * SCAN_B + threadIdx.x;
    int v = (gid < NROWS) ? g_counts[gid] : 0;
    s[threadIdx.x] = v;
    __syncthreads();
    #pragma unroll
    for (int off = 1; off < SCAN_B; off <<= 1) {
        int t = (threadIdx.x >= off) ? s[threadIdx.x - off] : 0;
        __syncthreads();
        s[threadIdx.x] += t;
        __syncthreads();
    }
    if (gid < NROWS) g_rowptr[gid] = s[threadIdx.x] - v;   // exclusive, block-local
    if (threadIdx.x == SCAN_B - 1) g_partials[blockIdx.x] = s[threadIdx.x];
}

// ---------------------------------------------------------------------------
// K3: each block reduces totals of all preceding blocks (98 ints) itself,
//     then adds the base. Produces final rowptr + scatter cursors.
// ---------------------------------------------------------------------------
__global__ void scan3_kernel()
{
    __shared__ int s[128];
    int t = threadIdx.x;
    if (t < 128) s[t] = (t < blockIdx.x && t < NBLK) ? g_partials[t] : 0;
    __syncthreads();
    #pragma unroll
    for (int off = 64; off > 0; off >>= 1) {
        if (t < off) s[t] += s[t + off];
        __syncthreads();
    }
    int base = s[0];

    int gid = blockIdx.x * SCAN_B + t;
    if (gid < NROWS) {
        int p = g_rowptr[gid] + base;
        g_rowptr[gid] = p;
        g_counts[gid] = p;     // scatter cursor
    }
}

// ---------------------------------------------------------------------------
// K4: scatter edges into CSR order, 4 edges per thread (MLP=4 on atomics).
// ---------------------------------------------------------------------------
__global__ void scatter_kernel(const int4* __restrict__ row4,
                               const int4* __restrict__ col4,
                               const float4* __restrict__ vals4)
{
    int i = blockIdx.x * blockDim.x + threadIdx.x;
    if (i < NNZ_E / 4) {
        int4   r = __ldg(row4 + i);
        int4   c = __ldg(col4 + i);
        float4 v = __ldg(vals4 + i);
        int p0 = atomicAdd(&g_counts[r.x], 1);
        int p1 = atomicAdd(&g_counts[r.y], 1);
        int p2 = atomicAdd(&g_counts[r.z], 1);
        int p3 = atomicAdd(&g_counts[r.w], 1);
        g_meta[p0] = make_int2(c.x, __float_as_int(v.x));
        g_meta[p1] = make_int2(c.y, __float_as_int(v.y));
        g_meta[p2] = make_int2(c.z, __float_as_int(v.z));
        g_meta[p3] = make_int2(c.w, __float_as_int(v.w));
    }
}

// ---------------------------------------------------------------------------
// Helper: fma 4 halves (uint2) scaled by v into acc (float4).
// ---------------------------------------------------------------------------
__device__ __forceinline__ void fma4(float4& acc, uint2 u, float v)
{
    float2 a = __half22float2(*reinterpret_cast<__half2*>(&u.x));
    float2 b = __half22float2(*reinterpret_cast<__half2*>(&u.y));
    acc.x = fmaf(v, a.x, acc.x); acc.y = fmaf(v, a.y, acc.y);
    acc.z = fmaf(v, b.x, acc.z); acc.w = fmaf(v, b.y, acc.w);
}

// ---------------------------------------------------------------------------
// K5: CSR SpMM with FP16 GATHERS, fp32 accumulation — EXACT R9 inner loop
//     (3-deep pipeline, half-warps on alternating edges; proven optimum
//      across R8/R10/R11 perturbation experiments — frozen).
//     Launched with TPB=128 (4 warps/block) to reduce block-level
//     row-degree skew (Poisson(32) max-of-8 -> max-of-4).
//   SRC: gather source selected device-side (0=g_embh, 1=g_e1h).
//   WRITE_H: also g_e1h[r,:] = fp16(y[r,:])   (layer 1 -> feeds layer 2)
//   FUSE:    also summed[r,:] = e0 + e1 + y   (layer 2)
// ---------------------------------------------------------------------------
template <int SRC, bool WRITE_H, bool FUSE>
__global__ void __launch_bounds__(128)
spmm_csr_kernel(float4* __restrict__ y,
                const float4* __restrict__ e0,
                const float4* __restrict__ e1,
                float4* __restrict__ summed)
{
    const uint2* __restrict__ xh = (SRC == 0) ? g_embh : g_e1h;

    int warp = (blockIdx.x * blockDim.x + threadIdx.x) >> 5;
    int lane = threadIdx.x & 31;
    int j    = lane & 15;        // uint2 slot within the 128B fp16 row
    int half = lane >> 4;        // 0 or 1: which edge of the pair
    if (warp >= NROWS) return;
    int r = warp;

    int beg = g_rowptr[r];
    int end = g_rowptr[r + 1];

    float4 acc = make_float4(0.f, 0.f, 0.f, 0.f);
    int e = beg + half;          // this thread's edge stream: e, e+2, e+4, ...

    // 3-deep: edges e, e+2, e+4 in flight -> 6 edges per warp concurrently
    for (; e + 4 < end; e += 6) {
        int2 m0 = __ldg(&g_meta[e]);
        int2 m1 = __ldg(&g_meta[e + 2]);
        int2 m2 = __ldg(&g_meta[e + 4]);
        uint2 u0 = __ldg(xh + (size_t)m0.x * 16 + j);
        uint2 u1 = __ldg(xh + (size_t)m1.x * 16 + j);
        uint2 u2 = __ldg(xh + (size_t)m2.x * 16 + j);
        fma4(acc, u0, __int_as_float(m0.y));
        fma4(acc, u1, __int_as_float(m1.y));
        fma4(acc, u2, __int_as_float(m2.y));
    }
    // 2-deep remainder
    if (e + 2 < end) {
        int2 m0 = __ldg(&g_meta[e]);
        int2 m1 = __ldg(&g_meta[e + 2]);
        uint2 u0 = __ldg(xh + (size_t)m0.x * 16 + j);
        uint2 u1 = __ldg(xh + (size_t)m1.x * 16 + j);
        fma4(acc, u0, __int_as_float(m0.y));
        fma4(acc, u1, __int_as_float(m1.y));
        e += 4;
    }
    if (e < end) {
        int2 m0 = __ldg(&g_meta[e]);
        uint2 u0 = __ldg(xh + (size_t)m0.x * 16 + j);
        fma4(acc, u0, __int_as_float(m0.y));
    }

    // combine the two half-warp partials
    acc.x += __shfl_xor_sync(0xffffffffu, acc.x, 16);
    acc.y += __shfl_xor_sync(0xffffffffu, acc.y, 16);
    acc.z += __shfl_xor_sync(0xffffffffu, acc.z, 16);
    acc.w += __shfl_xor_sync(0xffffffffu, acc.w, 16);

    if (half == 0) {
        size_t o = (size_t)r * 16 + j;
        y[o] = acc;
        if (WRITE_H) {
            __half2 h0 = __floats2half2_rn(acc.x, acc.y);
            __half2 h1 = __floats2half2_rn(acc.z, acc.w);
            uint2 u;
            u.x = *reinterpret_cast<unsigned*>(&h0);
            u.y = *reinterpret_cast<unsigned*>(&h1);
            g_e1h[o] = u;
        }
        if (FUSE) {
            float4 a = __ldg(e0 + o);
            float4 b = __ldg(e1 + o);
            float4 s;
            s.x = a.x + b.x + acc.x;
            s.y = a.y + b.y + acc.y;
            s.z = a.z + b.z + acc.z;
            s.w = a.w + b.w + acc.w;
            summed[o] = s;
        }
    }
}

// ---------------------------------------------------------------------------
// Launch sequence (default stream, graph-capturable, no allocations):
//   zero -> prep+hist -> scan1 -> scan3 -> scatter -> spmm L1 -> spmm L2
// ---------------------------------------------------------------------------
extern "C" void kernel_launch(void* const* d_in, const int* in_sizes, int n_in,
                              void* d_out, int out_size)
{
    const int*   row  = (const int*)d_in[0];
    const int*   col  = (const int*)d_in[1];
    const float* vals = (const float*)d_in[2];
    const float* emb  = (const float*)d_in[3];

    float* out = (float*)d_out;
    float4* summed = (float4*)out;
    float4* e0 = (float4*)(out + (size_t)ND);
    float4* e1 = (float4*)(out + (size_t)2 * ND);
    float4* e2 = (float4*)(out + (size_t)3 * ND);

    const int TPB = 256;

    // K0: zero counts
    zero_kernel<<<(NROWS + TPB - 1) / TPB, TPB>>>();

    // K1: e0 copy + fp16 conversion + histogram (fused)
    prep_hist_kernel<<<(ND4 + TPB - 1) / TPB, TPB>>>(
        (const float4*)emb, e0, (const int4*)row);

    // K2/K3: exclusive scan -> rowptr + cursors
    scan1_kernel<<<NBLK, SCAN_B>>>();
    scan3_kernel<<<NBLK, SCAN_B>>>();

    // K4: scatter to CSR
    scatter_kernel<<<(NNZ_E / 4 + TPB - 1) / TPB, TPB>>>(
        (const int4*)row, (const int4*)col, (const float4*)vals);

    // K5/K6: warp per row, fp16 uint2 gathers, 3-deep pipeline, TPB=128
    const int SPMM_TPB = 128;
    const int WARPS_PER_BLOCK = SPMM_TPB / 32;
    int spmm_blocks = (NROWS + WARPS_PER_BLOCK - 1) / WARPS_PER_BLOCK;

    // layer 1: e1 = A @ emb (gather g_embh), also g_e1h = fp16(e1)
    spmm_csr_kernel<0, true, false><<<spmm_blocks, SPMM_TPB>>>(
        e1, nullptr, nullptr, nullptr);

    // layer 2: e2 = A @ e1 (gather g_e1h), fused summed = e0 + e1 + e2
    spmm_csr_kernel<1, false, true><<<spmm_blocks, SPMM_TPB>>>(
        e2, (const float4*)e0, (const float4*)e1, summed);
}

// round 15
// speedup vs baseline: 1.1053x; 1.0158x over previous
#include <cuda_runtime.h>
#include <cuda_fp16.h>
#include <cstdint>

// Problem constants (match reference_code)
#define NROWS 100001
#define DIM   64
#define NNZ_E 3200000
#define ND    (NROWS * DIM)          // floats per segment
#define ND4   (ND / 4)               // float4 / uint2 granules per segment
#define SCAN_B 1024
#define NBLK  ((NROWS + SCAN_B - 1) / SCAN_B)   // 98

// ---------------------------------------------------------------------------
// Static device scratch. Referenced ONLY inside device code (R6 lesson:
// passing a __device__ symbol as a host-side kernel arg gives garbage).
// ---------------------------------------------------------------------------
__device__ int   g_counts[NROWS];       // histogram, then scatter cursors
__device__ int   g_rowptr[NROWS + 1];   // CSR row pointers (exclusive scan)
__device__ int   g_partials[NBLK];      // scan block totals
__device__ int2  g_meta[NNZ_E];         // CSR-ordered (col, val-bits), 25.6MB
__device__ uint2 g_embh[ND4];           // emb in fp16 (4 halves/uint2), 12.8MB
__device__ uint2 g_e1h[ND4];            // e1  in fp16, 12.8MB

// ---------------------------------------------------------------------------
// K0: zero histogram (must complete before prep_hist increments).
// ---------------------------------------------------------------------------
__global__ void zero_kernel()
{
    int i = blockIdx.x * blockDim.x + threadIdx.x;
    if (i < NROWS) g_counts[i] = 0;
    if (i == 0) g_rowptr[NROWS] = NNZ_E;
}

// ---------------------------------------------------------------------------
// K1: fused prep + hist.
//   i < ND4:     e0 = emb (fp32 copy), embh = fp16(emb)
//   i < NNZ/4:   histogram 4 edges (ND4 = 1.6M >= NNZ/4 = 800K)
// ---------------------------------------------------------------------------
__global__ void prep_hist_kernel(const float4* __restrict__ emb,
                                 float4* __restrict__ e0,
                                 const int4* __restrict__ row4)
{
    int i = blockIdx.x * blockDim.x + threadIdx.x;
    if (i < ND4) {
        float4 v = __ldg(emb + i);
        e0[i] = v;
        __half2 h0 = __floats2half2_rn(v.x, v.y);
        __half2 h1 = __floats2half2_rn(v.z, v.w);
        uint2 u;
        u.x = *reinterpret_cast<unsigned*>(&h0);
        u.y = *reinterpret_cast<unsigned*>(&h1);
        g_embh[i] = u;
    }
    if (i < NNZ_E / 4) {
        int4 r = __ldg(row4 + i);
        atomicAdd(&g_counts[r.x], 1);
        atomicAdd(&g_counts[r.y], 1);
        atomicAdd(&g_counts[r.z], 1);
        atomicAdd(&g_counts[r.w], 1);
    }
}

// ---------------------------------------------------------------------------
// K2: per-block exclusive scan of counts; block totals to g_partials.
// ---------------------------------------------------------------------------
__global__ void scan1_kernel()
{
    __shared__ int s[SCAN_B];
    int gid = blockIdx.x * SCAN_B + threadIdx.x;
    int v = (gid < NROWS) ? g_counts[gid] : 0;
    s[threadIdx.x] = v;
    __syncthreads();
    #pragma unroll
    for (int off = 1; off < SCAN_B; off <<= 1) {
        int t = (threadIdx.x >= off) ? s[threadIdx.x - off] : 0;
        __syncthreads();
        s[threadIdx.x] += t;
        __syncthreads();
    }
    if (gid < NROWS) g_rowptr[gid] = s[threadIdx.x] - v;   // exclusive, block-local
    if (threadIdx.x == SCAN_B - 1) g_partials[blockIdx.x] = s[threadIdx.x];
}

// ---------------------------------------------------------------------------
// K3: each block reduces totals of all preceding blocks (98 ints) itself,
//     then adds the base. Produces final rowptr + scatter cursors.
// ---------------------------------------------------------------------------
__global__ void scan3_kernel()
{
    __shared__ int s[128];
    int t = threadIdx.x;
    if (t < 128) s[t] = (t < blockIdx.x && t < NBLK) ? g_partials[t] : 0;
    __syncthreads();
    #pragma unroll
    for (int off = 64; off > 0; off >>= 1) {
        if (t < off) s[t] += s[t + off];
        __syncthreads();
    }
    int base = s[0];

    int gid = blockIdx.x * SCAN_B + t;
    if (gid < NROWS) {
        int p = g_rowptr[gid] + base;
        g_rowptr[gid] = p;
        g_counts[gid] = p;     // scatter cursor
    }
}

// ---------------------------------------------------------------------------
// K4: scatter edges into CSR order, 4 edges per thread (MLP=4 on atomics).
// ---------------------------------------------------------------------------
__global__ void scatter_kernel(const int4* __restrict__ row4,
                               const int4* __restrict__ col4,
                               const float4* __restrict__ vals4)
{
    int i = blockIdx.x * blockDim.x + threadIdx.x;
    if (i < NNZ_E / 4) {
        int4   r = __ldg(row4 + i);
        int4   c = __ldg(col4 + i);
        float4 v = __ldg(vals4 + i);
        int p0 = atomicAdd(&g_counts[r.x], 1);
        int p1 = atomicAdd(&g_counts[r.y], 1);
        int p2 = atomicAdd(&g_counts[r.z], 1);
        int p3 = atomicAdd(&g_counts[r.w], 1);
        g_meta[p0] = make_int2(c.x, __float_as_int(v.x));
        g_meta[p1] = make_int2(c.y, __float_as_int(v.y));
        g_meta[p2] = make_int2(c.z, __float_as_int(v.z));
        g_meta[p3] = make_int2(c.w, __float_as_int(v.w));
    }
}

// ---------------------------------------------------------------------------
// Helpers.
// ---------------------------------------------------------------------------
__device__ __forceinline__ void fma4(float4& acc, uint2 u, float v)
{
    float2 a = __half22float2(*reinterpret_cast<__half2*>(&u.x));
    float2 b = __half22float2(*reinterpret_cast<__half2*>(&u.y));
    acc.x = fmaf(v, a.x, acc.x); acc.y = fmaf(v, a.y, acc.y);
    acc.z = fmaf(v, b.x, acc.z); acc.w = fmaf(v, b.y, acc.w);
}

__device__ __forceinline__ float4 h4_to_f4(uint2 u)
{
    float2 a = __half22float2(*reinterpret_cast<__half2*>(&u.x));
    float2 b = __half22float2(*reinterpret_cast<__half2*>(&u.y));
    return make_float4(a.x, a.y, b.x, b.y);
}

// ---------------------------------------------------------------------------
// K5: CSR SpMM with FP16 GATHERS, fp32 accumulation — EXACT R9 inner loop
//     (3-deep pipeline, half-warps on alternating edges; frozen per
//      R8/R10/R11 perturbation evidence). TPB=128 (R14 win: less degree skew).
//   SRC: gather source selected device-side (0=g_embh, 1=g_e1h).
//   WRITE_H: also g_e1h[r,:] = fp16(y[r,:])   (layer 1 -> feeds layer 2)
//   FUSE:    also summed[r,:] = embh + e1h + y  (fp16 shadows, L2-hot;
//            their quantization is <3e-5 of |summed| since |e2|>>|e1|>>|e0|)
// ---------------------------------------------------------------------------
template <int SRC, bool WRITE_H, bool FUSE>
__global__ void __launch_bounds__(128)
spmm_csr_kernel(float4* __restrict__ y,
                float4* __restrict__ summed)
{
    const uint2* __restrict__ xh = (SRC == 0) ? g_embh : g_e1h;

    int warp = (blockIdx.x * blockDim.x + threadIdx.x) >> 5;
    int lane = threadIdx.x & 31;
    int j    = lane & 15;        // uint2 slot within the 128B fp16 row
    int half = lane >> 4;        // 0 or 1: which edge of the pair
    if (warp >= NROWS) return;
    int r = warp;

    int beg = g_rowptr[r];
    int end = g_rowptr[r + 1];

    float4 acc = make_float4(0.f, 0.f, 0.f, 0.f);
    int e = beg + half;          // this thread's edge stream: e, e+2, e+4, ...

    // 3-deep: edges e, e+2, e+4 in flight -> 6 edges per warp concurrently
    for (; e + 4 < end; e += 6) {
        int2 m0 = __ldg(&g_meta[e]);
        int2 m1 = __ldg(&g_meta[e + 2]);
        int2 m2 = __ldg(&g_meta[e + 4]);
        uint2 u0 = __ldg(xh + (size_t)m0.x * 16 + j);
        uint2 u1 = __ldg(xh + (size_t)m1.x * 16 + j);
        uint2 u2 = __ldg(xh + (size_t)m2.x * 16 + j);
        fma4(acc, u0, __int_as_float(m0.y));
        fma4(acc, u1, __int_as_float(m1.y));
        fma4(acc, u2, __int_as_float(m2.y));
    }
    // 2-deep remainder
    if (e + 2 < end) {
        int2 m0 = __ldg(&g_meta[e]);
        int2 m1 = __ldg(&g_meta[e + 2]);
        uint2 u0 = __ldg(xh + (size_t)m0.x * 16 + j);
        uint2 u1 = __ldg(xh + (size_t)m1.x * 16 + j);
        fma4(acc, u0, __int_as_float(m0.y));
        fma4(acc, u1, __int_as_float(m1.y));
        e += 4;
    }
    if (e < end) {
        int2 m0 = __ldg(&g_meta[e]);
        uint2 u0 = __ldg(xh + (size_t)m0.x * 16 + j);
        fma4(acc, u0, __int_as_float(m0.y));
    }

    // combine the two half-warp partials
    acc.x += __shfl_xor_sync(0xffffffffu, acc.x, 16);
    acc.y += __shfl_xor_sync(0xffffffffu, acc.y, 16);
    acc.z += __shfl_xor_sync(0xffffffffu, acc.z, 16);
    acc.w += __shfl_xor_sync(0xffffffffu, acc.w, 16);

    if (half == 0) {
        size_t o = (size_t)r * 16 + j;
        y[o] = acc;
        if (WRITE_H) {
            __half2 h0 = __floats2half2_rn(acc.x, acc.y);
            __half2 h1 = __floats2half2_rn(acc.z, acc.w);
            uint2 u;
            u.x = *reinterpret_cast<unsigned*>(&h0);
            u.y = *reinterpret_cast<unsigned*>(&h1);
            g_e1h[o] = u;
        }
        if (FUSE) {
            float4 a = h4_to_f4(__ldg(&g_embh[o]));   // e0 (fp16 shadow, hot)
            float4 b = h4_to_f4(__ldg(&g_e1h[o]));    // e1 (fp16 shadow, hot)
            float4 s;
            s.x = a.x + b.x + acc.x;
            s.y = a.y + b.y + acc.y;
            s.z = a.z + b.z + acc.z;
            s.w = a.w + b.w + acc.w;
            summed[o] = s;
        }
    }
}

// ---------------------------------------------------------------------------
// Launch sequence (default stream, graph-capturable, no allocations):
//   zero -> prep+hist -> scan1 -> scan3 -> scatter -> spmm L1 -> spmm L2
// ---------------------------------------------------------------------------
extern "C" void kernel_launch(void* const* d_in, const int* in_sizes, int n_in,
                              void* d_out, int out_size)
{
    const int*   row  = (const int*)d_in[0];
    const int*   col  = (const int*)d_in[1];
    const float* vals = (const float*)d_in[2];
    const float* emb  = (const float*)d_in[3];

    float* out = (float*)d_out;
    float4* summed = (float4*)out;
    float4* e0 = (float4*)(out + (size_t)ND);
    float4* e1 = (float4*)(out + (size_t)2 * ND);
    float4* e2 = (float4*)(out + (size_t)3 * ND);
    (void)e1;

    const int TPB = 256;

    // K0: zero counts
    zero_kernel<<<(NROWS + TPB - 1) / TPB, TPB>>>();

    // K1: e0 copy + fp16 conversion + histogram (fused)
    prep_hist_kernel<<<(ND4 + TPB - 1) / TPB, TPB>>>(
        (const float4*)emb, e0, (const int4*)row);

    // K2/K3: exclusive scan -> rowptr + cursors
    scan1_kernel<<<NBLK, SCAN_B>>>();
    scan3_kernel<<<NBLK, SCAN_B>>>();

    // K4: scatter to CSR
    scatter_kernel<<<(NNZ_E / 4 + TPB - 1) / TPB, TPB>>>(
        (const int4*)row, (const int4*)col, (const float4*)vals);

    // K5/K6: warp per row, fp16 uint2 gathers, 3-deep pipeline, TPB=128
    const int SPMM_TPB = 128;
    const int WARPS_PER_BLOCK = SPMM_TPB / 32;
    int spmm_blocks = (NROWS + WARPS_PER_BLOCK - 1) / WARPS_PER_BLOCK;

    // layer 1: e1 = A @ emb (gather g_embh), also g_e1h = fp16(e1)
    spmm_csr_kernel<0, true, false><<<spmm_blocks, SPMM_TPB>>>(
        (float4*)(out + (size_t)2 * ND), nullptr);

    // layer 2: e2 = A @ e1 (gather g_e1h), fused summed = e0 + e1 + e2
    //          (e0/e1 addends read from the L2-hot fp16 shadows)
    spmm_csr_kernel<1, false, true><<<spmm_blocks, SPMM_TPB>>>(e2, summed);
}

// round 16
// speedup vs baseline: 1.1086x; 1.0031x over previous
#include <cuda_runtime.h>
#include <cuda_fp16.h>
#include <cstdint>

// Problem constants (match reference_code)
#define NROWS 100001
#define DIM   64
#define NNZ_E 3200000
#define ND    (NROWS * DIM)          // floats per segment
#define ND4   (ND / 4)               // float4 / uint2 granules per segment
#define SCAN_B 1024
#define NBLK  ((NROWS + SCAN_B - 1) / SCAN_B)   // 98

// ---------------------------------------------------------------------------
// Static device scratch. Referenced ONLY inside device code (R6 lesson:
// passing a __device__ symbol as a host-side kernel arg gives garbage).
// ---------------------------------------------------------------------------
__device__ int   g_counts[NROWS];       // histogram, then scatter cursors
__device__ int   g_rowptr[NROWS + 1];   // CSR row pointers (exclusive scan)
__device__ int   g_partials[NBLK];      // scan block totals
__device__ int2  g_meta[NNZ_E];         // CSR-ordered (col, val-bits), 25.6MB
__device__ uint2 g_embh[ND4];           // emb in fp16 (4 halves/uint2), 12.8MB
__device__ uint2 g_e1h[ND4];            // e1  in fp16, 12.8MB

// ---------------------------------------------------------------------------
// K0: zero histogram (must complete before prep_hist increments).
// ---------------------------------------------------------------------------
__global__ void zero_kernel()
{
    int i = blockIdx.x * blockDim.x + threadIdx.x;
    if (i < NROWS) g_counts[i] = 0;
    if (i == 0) g_rowptr[NROWS] = NNZ_E;
}

// ---------------------------------------------------------------------------
// K1: fused prep + hist.
//   i < ND4:     e0 = emb (fp32 copy), embh = fp16(emb)
//   i < NNZ/4:   histogram 4 edges (ND4 = 1.6M >= NNZ/4 = 800K)
// ---------------------------------------------------------------------------
__global__ void prep_hist_kernel(const float4* __restrict__ emb,
                                 float4* __restrict__ e0,
                                 const int4* __restrict__ row4)
{
    int i = blockIdx.x * blockDim.x + threadIdx.x;
    if (i < ND4) {
        float4 v = __ldg(emb + i);
        e0[i] = v;
        __half2 h0 = __floats2half2_rn(v.x, v.y);
        __half2 h1 = __floats2half2_rn(v.z, v.w);
        uint2 u;
        u.x = *reinterpret_cast<unsigned*>(&h0);
        u.y = *reinterpret_cast<unsigned*>(&h1);
        g_embh[i] = u;
    }
    if (i < NNZ_E / 4) {
        int4 r = __ldg(row4 + i);
        atomicAdd(&g_counts[r.x], 1);
        atomicAdd(&g_counts[r.y], 1);
        atomicAdd(&g_counts[r.z], 1);
        atomicAdd(&g_counts[r.w], 1);
    }
}

// ---------------------------------------------------------------------------
// K2: per-block exclusive scan of counts; block totals to g_partials.
// ---------------------------------------------------------------------------
__global__ void scan1_kernel()
{
    __shared__ int s[SCAN_B];
    int gid = blockIdx.x * SCAN_B + threadIdx.x;
    int v = (gid < NROWS) ? g_counts[gid] : 0;
    s[threadIdx.x] = v;
    __syncthreads();
    #pragma unroll
    for (int off = 1; off < SCAN_B; off <<= 1) {
        int t = (threadIdx.x >= off) ? s[threadIdx.x - off] : 0;
        __syncthreads();
        s[threadIdx.x] += t;
        __syncthreads();
    }
    if (gid < NROWS) g_rowptr[gid] = s[threadIdx.x] - v;   // exclusive, block-local
    if (threadIdx.x == SCAN_B - 1) g_partials[blockIdx.x] = s[threadIdx.x];
}

// ---------------------------------------------------------------------------
// K3: each block reduces totals of all preceding blocks (98 ints) itself,
//     then adds the base. Produces final rowptr + scatter cursors.
// ---------------------------------------------------------------------------
__global__ void scan3_kernel()
{
    __shared__ int s[128];
    int t = threadIdx.x;
    if (t < 128) s[t] = (t < blockIdx.x && t < NBLK) ? g_partials[t] : 0;
    __syncthreads();
    #pragma unroll
    for (int off = 64; off > 0; off >>= 1) {
        if (t < off) s[t] += s[t + off];
        __syncthreads();
    }
    int base = s[0];

    int gid = blockIdx.x * SCAN_B + t;
    if (gid < NROWS) {
        int p = g_rowptr[gid] + base;
        g_rowptr[gid] = p;
        g_counts[gid] = p;     // scatter cursor
    }
}

// ---------------------------------------------------------------------------
// K4: scatter edges into CSR order, 4 edges per thread (MLP=4 on atomics).
// ---------------------------------------------------------------------------
__global__ void scatter_kernel(const int4* __restrict__ row4,
                               const int4* __restrict__ col4,
                               const float4* __restrict__ vals4)
{
    int i = blockIdx.x * blockDim.x + threadIdx.x;
    if (i < NNZ_E / 4) {
        int4   r = __ldg(row4 + i);
        int4   c = __ldg(col4 + i);
        float4 v = __ldg(vals4 + i);
        int p0 = atomicAdd(&g_counts[r.x], 1);
        int p1 = atomicAdd(&g_counts[r.y], 1);
        int p2 = atomicAdd(&g_counts[r.z], 1);
        int p3 = atomicAdd(&g_counts[r.w], 1);
        g_meta[p0] = make_int2(c.x, __float_as_int(v.x));
        g_meta[p1] = make_int2(c.y, __float_as_int(v.y));
        g_meta[p2] = make_int2(c.z, __float_as_int(v.z));
        g_meta[p3] = make_int2(c.w, __float_as_int(v.w));
    }
}

// ---------------------------------------------------------------------------
// Helpers.
// ---------------------------------------------------------------------------
__device__ __forceinline__ void fma4(float4& acc, uint2 u, float v)
{
    float2 a = __half22float2(*reinterpret_cast<__half2*>(&u.x));
    float2 b = __half22float2(*reinterpret_cast<__half2*>(&u.y));
    acc.x = fmaf(v, a.x, acc.x); acc.y = fmaf(v, a.y, acc.y);
    acc.z = fmaf(v, b.x, acc.z); acc.w = fmaf(v, b.y, acc.w);
}

__device__ __forceinline__ float4 h4_to_f4(uint2 u)
{
    float2 a = __half22float2(*reinterpret_cast<__half2*>(&u.x));
    float2 b = __half22float2(*reinterpret_cast<__half2*>(&u.y));
    return make_float4(a.x, a.y, b.x, b.y);
}

// ---------------------------------------------------------------------------
// K5: CSR SpMM with FP16 GATHERS, fp32 accumulation — EXACT R9 inner loop
//     (3-deep pipeline, half-warps on alternating edges; frozen per
//      R8/R10/R11 perturbation evidence). TPB=64: R14 showed 256->128 wins
//      via reduced block-level degree skew; this is the next notch
//      (Poisson(32) max-of-2 per block), occupancy preserved (32 CTA/SM).
//   SRC: gather source selected device-side (0=g_embh, 1=g_e1h).
//   WRITE_H: also g_e1h[r,:] = fp16(y[r,:])   (layer 1 -> feeds layer 2)
//   FUSE:    also summed[r,:] = embh + e1h + y  (fp16 shadows, L2-hot)
// ---------------------------------------------------------------------------
template <int SRC, bool WRITE_H, bool FUSE>
__global__ void __launch_bounds__(64)
spmm_csr_kernel(float4* __restrict__ y,
                float4* __restrict__ summed)
{
    const uint2* __restrict__ xh = (SRC == 0) ? g_embh : g_e1h;

    int warp = (blockIdx.x * blockDim.x + threadIdx.x) >> 5;
    int lane = threadIdx.x & 31;
    int j    = lane & 15;        // uint2 slot within the 128B fp16 row
    int half = lane >> 4;        // 0 or 1: which edge of the pair
    if (warp >= NROWS) return;
    int r = warp;

    int beg = g_rowptr[r];
    int end = g_rowptr[r + 1];

    float4 acc = make_float4(0.f, 0.f, 0.f, 0.f);
    int e = beg + half;          // this thread's edge stream: e, e+2, e+4, ...

    // 3-deep: edges e, e+2, e+4 in flight -> 6 edges per warp concurrently
    for (; e + 4 < end; e += 6) {
        int2 m0 = __ldg(&g_meta[e]);
        int2 m1 = __ldg(&g_meta[e + 2]);
        int2 m2 = __ldg(&g_meta[e + 4]);
        uint2 u0 = __ldg(xh + (size_t)m0.x * 16 + j);
        uint2 u1 = __ldg(xh + (size_t)m1.x * 16 + j);
        uint2 u2 = __ldg(xh + (size_t)m2.x * 16 + j);
        fma4(acc, u0, __int_as_float(m0.y));
        fma4(acc, u1, __int_as_float(m1.y));
        fma4(acc, u2, __int_as_float(m2.y));
    }
    // 2-deep remainder
    if (e + 2 < end) {
        int2 m0 = __ldg(&g_meta[e]);
        int2 m1 = __ldg(&g_meta[e + 2]);
        uint2 u0 = __ldg(xh + (size_t)m0.x * 16 + j);
        uint2 u1 = __ldg(xh + (size_t)m1.x * 16 + j);
        fma4(acc, u0, __int_as_float(m0.y));
        fma4(acc, u1, __int_as_float(m1.y));
        e += 4;
    }
    if (e < end) {
        int2 m0 = __ldg(&g_meta[e]);
        uint2 u0 = __ldg(xh + (size_t)m0.x * 16 + j);
        fma4(acc, u0, __int_as_float(m0.y));
    }

    // combine the two half-warp partials
    acc.x += __shfl_xor_sync(0xffffffffu, acc.x, 16);
    acc.y += __shfl_xor_sync(0xffffffffu, acc.y, 16);
    acc.z += __shfl_xor_sync(0xffffffffu, acc.z, 16);
    acc.w += __shfl_xor_sync(0xffffffffu, acc.w, 16);

    if (half == 0) {
        size_t o = (size_t)r * 16 + j;
        y[o] = acc;
        if (WRITE_H) {
            __half2 h0 = __floats2half2_rn(acc.x, acc.y);
            __half2 h1 = __floats2half2_rn(acc.z, acc.w);
            uint2 u;
            u.x = *reinterpret_cast<unsigned*>(&h0);
            u.y = *reinterpret_cast<unsigned*>(&h1);
            g_e1h[o] = u;
        }
        if (FUSE) {
            float4 a = h4_to_f4(__ldg(&g_embh[o]));   // e0 (fp16 shadow, hot)
            float4 b = h4_to_f4(__ldg(&g_e1h[o]));    // e1 (fp16 shadow, hot)
            float4 s;
            s.x = a.x + b.x + acc.x;
            s.y = a.y + b.y + acc.y;
            s.z = a.z + b.z + acc.z;
            s.w = a.w + b.w + acc.w;
            summed[o] = s;
        }
    }
}

// ---------------------------------------------------------------------------
// Launch sequence (default stream, graph-capturable, no allocations):
//   zero -> prep+hist -> scan1 -> scan3 -> scatter -> spmm L1 -> spmm L2
// ---------------------------------------------------------------------------
extern "C" void kernel_launch(void* const* d_in, const int* in_sizes, int n_in,
                              void* d_out, int out_size)
{
    const int*   row  = (const int*)d_in[0];
    const int*   col  = (const int*)d_in[1];
    const float* vals = (const float*)d_in[2];
    const float* emb  = (const float*)d_in[3];

    float* out = (float*)d_out;
    float4* summed = (float4*)out;
    float4* e0 = (float4*)(out + (size_t)ND);
    float4* e1 = (float4*)(out + (size_t)2 * ND);
    float4* e2 = (float4*)(out + (size_t)3 * ND);

    const int TPB = 256;

    // K0: zero counts
    zero_kernel<<<(NROWS + TPB - 1) / TPB, TPB>>>();

    // K1: e0 copy + fp16 conversion + histogram (fused)
    prep_hist_kernel<<<(ND4 + TPB - 1) / TPB, TPB>>>(
        (const float4*)emb, e0, (const int4*)row);

    // K2/K3: exclusive scan -> rowptr + cursors
    scan1_kernel<<<NBLK, SCAN_B>>>();
    scan3_kernel<<<NBLK, SCAN_B>>>();

    // K4: scatter to CSR
    scatter_kernel<<<(NNZ_E / 4 + TPB - 1) / TPB, TPB>>>(
        (const int4*)row, (const int4*)col, (const float4*)vals);

    // K5/K6: warp per row, fp16 uint2 gathers, 3-deep pipeline, TPB=64
    const int SPMM_TPB = 64;
    const int WARPS_PER_BLOCK = SPMM_TPB / 32;
    int spmm_blocks = (NROWS + WARPS_PER_BLOCK - 1) / WARPS_PER_BLOCK;

    // layer 1: e1 = A @ emb (gather g_embh), also g_e1h = fp16(e1)
    spmm_csr_kernel<0, true, false><<<spmm_blocks, SPMM_TPB>>>(e1, nullptr);

    // layer 2: e2 = A @ e1 (gather g_e1h), fused summed = e0 + e1 + e2
    //          (e0/e1 addends read from the L2-hot fp16 shadows)
    spmm_csr_kernel<1, false, true><<<spmm_blocks, SPMM_TPB>>>(e2, summed);
}